// round 5
// baseline (speedup 1.0000x reference)
#include <cuda_runtime.h>
#include <math.h>

#define BSZ   2
#define NN    512
#define DIN   256
#define HEADS 8
#define DOUT  64
#define HD    512
#define ROWS  1024
#define ALPHA 0.2f

// ---------------- packed fp32x2 helpers (Blackwell FADD2/FFMA2) ----------------
struct __align__(8) F2 { float x, y; };

__device__ __forceinline__ F2 f2add(F2 a, F2 b) {
    F2 r;
    asm("add.rn.f32x2 %0, %1, %2;"
        : "=l"(*reinterpret_cast<unsigned long long*>(&r))
        : "l"(*reinterpret_cast<unsigned long long*>(&a)),
          "l"(*reinterpret_cast<unsigned long long*>(&b)));
    return r;
}
__device__ __forceinline__ F2 f2fma(F2 a, F2 b, F2 c) {
    F2 r;
    asm("fma.rn.f32x2 %0, %1, %2, %3;"
        : "=l"(*reinterpret_cast<unsigned long long*>(&r))
        : "l"(*reinterpret_cast<unsigned long long*>(&a)),
          "l"(*reinterpret_cast<unsigned long long*>(&b)),
          "l"(*reinterpret_cast<unsigned long long*>(&c)));
    return r;
}

// ---------------- device scratch ----------------
__device__ float g_src [ROWS * HD];
__device__ float g_tgt [ROWS * HD];
__device__ float g_skip[ROWS * HD];
__device__ float g_asrc[BSZ * HEADS * NN];
__device__ float g_atgt[BSZ * HEADS * NN];
__device__ float g_prob[BSZ * HEADS * NN * NN];   // normalized probs, 8 MB

#define APITCH 68     // As pitch (floats)
#define BPITCH 132    // Bs pitch (floats, duplicated F2 layout: 64 d -> 128 + pad)

// ---------------------------------------------------------------------------
// K1: three projections C = X @ W (X:[1024,256], W:[256,512])
// 64x64 tile, 256 threads, grid (8,16,3). micro 4n x 4d, k-slab 32, prefetch.
// As[k][n] (float4-readable pairs), Bs duplicated F2. 8 FFMA2 : 3 LDS.128 / k.
// Epilogue (z<2): rank-1 dots s_h . row -> g_asrc / g_atgt.
// ---------------------------------------------------------------------------
__global__ void __launch_bounds__(256) gemm3_kernel(
    const float* __restrict__ X,
    const float* __restrict__ Wsrc,
    const float* __restrict__ Wtgt,
    const float* __restrict__ Wskip,
    const float* __restrict__ scoring)
{
    __shared__ __align__(16) float As[32 * APITCH];
    __shared__ __align__(16) float Bs[32 * BPITCH];
    __shared__ float sh_sv[64];

    const int z = blockIdx.z;
    const float* W = (z == 0) ? Wsrc : (z == 1) ? Wtgt : Wskip;
    float* C = (z == 0) ? g_src : (z == 1) ? g_tgt : g_skip;

    const int rowBase = blockIdx.y * 64;
    const int colBase = blockIdx.x * 64;
    const int t  = threadIdx.x;

    const int nG = t >> 4;            // 0..15 -> 4 n rows
    const int dG = t & 15;            // 0..15 -> 4 d cols
    const int r0 = nG * 4;
    const int d0 = dG * 4;

    // loaders
    const int ak  = t & 31;           // A: k lane (coalesced)
    const int an0 = t >> 5;           // A: n base (+8i)
    const int bkk = t >> 4;           // B: k base (+16q)
    const int bc  = t & 15;           // B: float4 col

    if (t < 16)
        *(float4*)&sh_sv[t * 4] = *(const float4*)&scoring[colBase + t * 4];

    F2 acc[2][4];
#pragma unroll
    for (int p = 0; p < 2; p++)
#pragma unroll
        for (int j = 0; j < 4; j++) acc[p][j] = {0.f, 0.f};

    float  aR[8];
    float4 bR[2];

#pragma unroll
    for (int i = 0; i < 8; i++)
        aR[i] = X[(size_t)(rowBase + an0 + 8 * i) * DIN + ak];
#pragma unroll
    for (int q = 0; q < 2; q++)
        bR[q] = *(const float4*)&W[(size_t)(bkk + 16 * q) * HD + colBase + bc * 4];

    for (int s = 0; s < 8; s++) {
        __syncthreads();
#pragma unroll
        for (int i = 0; i < 8; i++)
            As[ak * APITCH + an0 + 8 * i] = aR[i];
#pragma unroll
        for (int q = 0; q < 2; q++) {
            float4 w4 = bR[q];
            float* bp = &Bs[(bkk + 16 * q) * BPITCH + bc * 8];
            *(float4*)bp       = make_float4(w4.x, w4.x, w4.y, w4.y);
            *(float4*)(bp + 4) = make_float4(w4.z, w4.z, w4.w, w4.w);
        }
        __syncthreads();

        if (s < 7) {
            const int k0 = (s + 1) * 32;
#pragma unroll
            for (int i = 0; i < 8; i++)
                aR[i] = X[(size_t)(rowBase + an0 + 8 * i) * DIN + k0 + ak];
#pragma unroll
            for (int q = 0; q < 2; q++)
                bR[q] = *(const float4*)&W[(size_t)(k0 + bkk + 16 * q) * HD + colBase + bc * 4];
        }

#pragma unroll
        for (int k = 0; k < 32; k++) {
            float4 a4  = *(const float4*)&As[k * APITCH + r0];
            float4 b01 = *(const float4*)&Bs[k * BPITCH + d0 * 2];
            float4 b23 = *(const float4*)&Bs[k * BPITCH + d0 * 2 + 4];
            F2 ap[2] = {{a4.x, a4.y}, {a4.z, a4.w}};
            F2 bb[4] = {{b01.x, b01.y}, {b01.z, b01.w}, {b23.x, b23.y}, {b23.z, b23.w}};
#pragma unroll
            for (int p = 0; p < 2; p++)
#pragma unroll
                for (int j = 0; j < 4; j++)
                    acc[p][j] = f2fma(ap[p], bb[j], acc[p][j]);
        }
    }

    // store C: 4 rows x 4 cols
#pragma unroll
    for (int p = 0; p < 2; p++) {
        float4 lo = make_float4(acc[p][0].x, acc[p][1].x, acc[p][2].x, acc[p][3].x);
        float4 hi = make_float4(acc[p][0].y, acc[p][1].y, acc[p][2].y, acc[p][3].y);
        *(float4*)&C[(size_t)(rowBase + r0 + 2 * p)     * HD + colBase + d0] = lo;
        *(float4*)&C[(size_t)(rowBase + r0 + 2 * p + 1) * HD + colBase + d0] = hi;
    }

    if (z < 2) {
        const float s0 = sh_sv[d0], s1 = sh_sv[d0 + 1],
                    s2 = sh_sv[d0 + 2], s3 = sh_sv[d0 + 3];
        float part[4];
#pragma unroll
        for (int p = 0; p < 2; p++) {
            part[2 * p]     = acc[p][0].x * s0 + acc[p][1].x * s1
                            + acc[p][2].x * s2 + acc[p][3].x * s3;
            part[2 * p + 1] = acc[p][0].y * s0 + acc[p][1].y * s1
                            + acc[p][2].y * s2 + acc[p][3].y * s3;
        }
#pragma unroll
        for (int o = 1; o <= 8; o <<= 1)
#pragma unroll
            for (int i = 0; i < 4; i++)
                part[i] += __shfl_xor_sync(0xffffffffu, part[i], o);
        if (dG == 0) {
            float* dst = (z == 0) ? g_asrc : g_atgt;
            const int hh = blockIdx.x;
#pragma unroll
            for (int i = 0; i < 4; i++) {
                int rG = rowBase + r0 + i;
                dst[((rG >> 9) * HEADS + hh) * NN + (rG & (NN - 1))] = part[i];
            }
        }
    }
}

// ---------------------------------------------------------------------------
// K2: scores + mask + softmax -> normalized probs to global.
// Block = (16 n, head, batch), 512 threads, grid (32, 8, 2).
// Thread: 4n x 4m (m strided by 128), d staged in chunks of 8, reg-prefetched.
// ---------------------------------------------------------------------------
#define TPITCH 10

__global__ void __launch_bounds__(512) score_kernel(
    const int*   __restrict__ adj,
    const float* __restrict__ scoring)
{
    __shared__ __align__(16) float BUF[512 * TPITCH];   // tgt stage [m][8d]
    __shared__ __align__(16) float sh_src[16 * 64];
    __shared__ float sh_atgt[512];
    __shared__ __align__(16) float sh_s[64];
    __shared__ float sh_asrc[16];
    __shared__ float REDM[4][4][4];
    __shared__ float REDS[4][4][4];

    const int t  = threadIdx.x;
    const int bn = blockIdx.x * 16;
    const int h  = blockIdx.y;
    const int b  = blockIdx.z;
    const int bh = b * HEADS + h;

    const int nG = t >> 7;          // 0..3 (4 n each)
    const int mG = t & 127;         // m = mG + 128*mm
    const int wg = (t >> 5) & 3;

    // ---- prologue ----
    if (t < 16) {
        float4 v = *(const float4*)&scoring[h * 64 + t * 4];
        v.x *= (1.f - ALPHA); v.y *= (1.f - ALPHA);
        v.z *= (1.f - ALPHA); v.w *= (1.f - ALPHA);
        *(float4*)&sh_s[t * 4] = v;
        sh_asrc[t] = g_asrc[bh * NN + bn + t];
    }
    if (t < 256) {
        int r = t >> 4, c = t & 15;
        *(float4*)&sh_src[r * 64 + c * 4] =
            *(const float4*)&g_src[(size_t)(b * NN + bn + r) * HD + h * 64 + c * 4];
    }
    sh_atgt[t] = g_atgt[bh * NN + t];

    F2 acc[4][4];
#pragma unroll
    for (int i = 0; i < 4; i++)
#pragma unroll
        for (int mm = 0; mm < 4; mm++) acc[i][mm] = {0.f, 0.f};

    float4 pf[2];
#pragma unroll
    for (int q = 0; q < 2; q++) {
        int f4 = t + 512 * q;
        int row = f4 >> 1, half = f4 & 1;
        pf[q] = *(const float4*)&g_tgt[(size_t)(b * NN + row) * HD + h * 64 + half * 4];
    }

    for (int chunk = 0; chunk < 8; chunk++) {
        __syncthreads();
#pragma unroll
        for (int q = 0; q < 2; q++) {
            int f4 = t + 512 * q;
            int row = f4 >> 1, half = f4 & 1;
            int base = row * TPITCH + half * 4;
            *(F2*)&BUF[base]     = {pf[q].x, pf[q].y};
            *(F2*)&BUF[base + 2] = {pf[q].z, pf[q].w};
        }
        __syncthreads();

        if (chunk < 7) {
            const int c8 = (chunk + 1) * 8;
#pragma unroll
            for (int q = 0; q < 2; q++) {
                int f4 = t + 512 * q;
                int row = f4 >> 1, half = f4 & 1;
                pf[q] = *(const float4*)
                    &g_tgt[(size_t)(b * NN + row) * HD + h * 64 + c8 + half * 4];
            }
        }

#pragma unroll
        for (int j = 0; j < 4; j++) {
            F2 sj = *(const F2*)&sh_s[chunk * 8 + j * 2];
            F2 srcv[4];
#pragma unroll
            for (int i = 0; i < 4; i++)
                srcv[i] = *(const F2*)&sh_src[(nG * 4 + i) * 64 + chunk * 8 + j * 2];
#pragma unroll
            for (int mm = 0; mm < 4; mm++) {
                F2 tv = *(const F2*)&BUF[(mG + 128 * mm) * TPITCH + j * 2];
#pragma unroll
                for (int i = 0; i < 4; i++) {
                    F2 u = f2add(srcv[i], tv);
                    u.x = fmaxf(u.x, 0.f);
                    u.y = fmaxf(u.y, 0.f);
                    acc[i][mm] = f2fma(sj, u, acc[i][mm]);
                }
            }
        }
    }

    // ---- finalize scores + mask (in registers) ----
    float a_n[4];
#pragma unroll
    for (int i = 0; i < 4; i++) a_n[i] = sh_asrc[nG * 4 + i];

    float p[4][4];
    float rm[4] = {-3.4e38f, -3.4e38f, -3.4e38f, -3.4e38f};
#pragma unroll
    for (int mm = 0; mm < 4; mm++) {
        const int m = mG + 128 * mm;
        const float bm = sh_atgt[m];
#pragma unroll
        for (int i = 0; i < 4; i++) {
            float s = acc[i][mm].x + acc[i][mm].y;
            s = fmaf(ALPHA, a_n[i] + bm, s);
            int av = adj[(size_t)(b * NN + bn + nG * 4 + i) * NN + m];
            s = (av == 0) ? s - 1.0e9f : s;
            p[i][mm] = s;
            rm[i] = fmaxf(rm[i], s);
        }
    }

    // ---- softmax: max ----
#pragma unroll
    for (int i = 0; i < 4; i++)
#pragma unroll
        for (int o = 16; o; o >>= 1)
            rm[i] = fmaxf(rm[i], __shfl_xor_sync(0xffffffffu, rm[i], o));
    if ((t & 31) == 0)
#pragma unroll
        for (int i = 0; i < 4; i++) REDM[nG][wg][i] = rm[i];
    __syncthreads();
#pragma unroll
    for (int i = 0; i < 4; i++)
        rm[i] = fmaxf(fmaxf(REDM[nG][0][i], REDM[nG][1][i]),
                      fmaxf(REDM[nG][2][i], REDM[nG][3][i]));

    // ---- exp + sum ----
    float ps[4] = {0.f, 0.f, 0.f, 0.f};
#pragma unroll
    for (int mm = 0; mm < 4; mm++)
#pragma unroll
        for (int i = 0; i < 4; i++) {
            float e = __expf(p[i][mm] - rm[i]);
            p[i][mm] = e;
            ps[i] += e;
        }
#pragma unroll
    for (int i = 0; i < 4; i++)
#pragma unroll
        for (int o = 16; o; o >>= 1)
            ps[i] += __shfl_xor_sync(0xffffffffu, ps[i], o);
    if ((t & 31) == 0)
#pragma unroll
        for (int i = 0; i < 4; i++) REDS[nG][wg][i] = ps[i];
    __syncthreads();

    float inv[4];
#pragma unroll
    for (int i = 0; i < 4; i++)
        inv[i] = 1.f / (REDS[nG][0][i] + REDS[nG][1][i] +
                        REDS[nG][2][i] + REDS[nG][3][i]);

    // ---- write normalized probs ----
#pragma unroll
    for (int i = 0; i < 4; i++) {
        const size_t rowOff = ((size_t)bh * NN + bn + nG * 4 + i) * NN;
#pragma unroll
        for (int mm = 0; mm < 4; mm++)
            g_prob[rowOff + mG + 128 * mm] = p[i][mm] * inv[i];
    }
}

// ---------------------------------------------------------------------------
// K3: aggregation GEMM  out[n,d] = probs[n,:] @ V[:,d]  (+skip+bias, ELU)
// Per (b,h): 512x64 output. Tile 64n x 64d, 256 threads, grid (8, 8, 2).
// ---------------------------------------------------------------------------
__global__ void __launch_bounds__(256) agg_kernel(
    const float* __restrict__ bias,
    float*       __restrict__ out)
{
    __shared__ __align__(16) float As[32 * APITCH];
    __shared__ __align__(16) float Bs[32 * BPITCH];

    const int rowBase = blockIdx.x * 64;   // n tile
    const int h = blockIdx.y;
    const int b = blockIdx.z;
    const int bh = b * HEADS + h;
    const int t = threadIdx.x;

    const int nG = t >> 4, dG = t & 15;
    const int r0 = nG * 4, d0 = dG * 4;
    const int ak  = t & 31;
    const int an0 = t >> 5;
    const int bkk = t >> 4;
    const int bc  = t & 15;

    const float* P = g_prob + (size_t)bh * NN * NN;
    const float* V = g_src + (size_t)b * NN * HD + h * 64;

    F2 acc[2][4];
#pragma unroll
    for (int p = 0; p < 2; p++)
#pragma unroll
        for (int j = 0; j < 4; j++) acc[p][j] = {0.f, 0.f};

    float  aR[8];
    float4 bR[2];
#pragma unroll
    for (int i = 0; i < 8; i++)
        aR[i] = P[(size_t)(rowBase + an0 + 8 * i) * NN + ak];
#pragma unroll
    for (int q = 0; q < 2; q++)
        bR[q] = *(const float4*)&V[(size_t)(bkk + 16 * q) * HD + bc * 4];

    for (int s = 0; s < 16; s++) {
        __syncthreads();
#pragma unroll
        for (int i = 0; i < 8; i++)
            As[ak * APITCH + an0 + 8 * i] = aR[i];
#pragma unroll
        for (int q = 0; q < 2; q++) {
            float4 w4 = bR[q];
            float* bp = &Bs[(bkk + 16 * q) * BPITCH + bc * 8];
            *(float4*)bp       = make_float4(w4.x, w4.x, w4.y, w4.y);
            *(float4*)(bp + 4) = make_float4(w4.z, w4.z, w4.w, w4.w);
        }
        __syncthreads();

        if (s < 15) {
            const int k0 = (s + 1) * 32;
#pragma unroll
            for (int i = 0; i < 8; i++)
                aR[i] = P[(size_t)(rowBase + an0 + 8 * i) * NN + k0 + ak];
#pragma unroll
            for (int q = 0; q < 2; q++)
                bR[q] = *(const float4*)&V[(size_t)(k0 + bkk + 16 * q) * HD + bc * 4];
        }

#pragma unroll
        for (int k = 0; k < 32; k++) {
            float4 a4  = *(const float4*)&As[k * APITCH + r0];
            float4 b01 = *(const float4*)&Bs[k * BPITCH + d0 * 2];
            float4 b23 = *(const float4*)&Bs[k * BPITCH + d0 * 2 + 4];
            F2 ap[2] = {{a4.x, a4.y}, {a4.z, a4.w}};
            F2 bb[4] = {{b01.x, b01.y}, {b01.z, b01.w}, {b23.x, b23.y}, {b23.z, b23.w}};
#pragma unroll
            for (int p = 0; p < 2; p++)
#pragma unroll
                for (int j = 0; j < 4; j++)
                    acc[p][j] = f2fma(ap[p], bb[j], acc[p][j]);
        }
    }

    // epilogue: + skip + bias, ELU, store
    float4 bi = *(const float4*)&bias[h * 64 + d0];
#pragma unroll
    for (int p = 0; p < 2; p++) {
#pragma unroll
        for (int hh = 0; hh < 2; hh++) {
            const int n = rowBase + r0 + 2 * p + hh;
            const size_t off = (size_t)(b * NN + n) * HD + h * 64 + d0;
            float4 sk = *(const float4*)&g_skip[off];
            float4 o;
            o.x = (hh ? acc[p][0].y : acc[p][0].x) + sk.x + bi.x;
            o.y = (hh ? acc[p][1].y : acc[p][1].x) + sk.y + bi.y;
            o.z = (hh ? acc[p][2].y : acc[p][2].x) + sk.z + bi.z;
            o.w = (hh ? acc[p][3].y : acc[p][3].x) + sk.w + bi.w;
            o.x = (o.x > 0.f) ? o.x : expm1f(o.x);
            o.y = (o.y > 0.f) ? o.y : expm1f(o.y);
            o.z = (o.z > 0.f) ? o.z : expm1f(o.z);
            o.w = (o.w > 0.f) ? o.w : expm1f(o.w);
            *(float4*)&out[off] = o;
        }
    }
}

// ---------------------------------------------------------------------------
// Optional second output: reference returns (out, adj)
// ---------------------------------------------------------------------------
__global__ void __launch_bounds__(256) copy_adj_vec_kernel(
    const int4* __restrict__ adj, float4* __restrict__ dst, int n4)
{
    int i = blockIdx.x * 256 + threadIdx.x;
    if (i < n4) {
        int4 v = adj[i];
        dst[i] = make_float4((float)v.x, (float)v.y, (float)v.z, (float)v.w);
    }
}
__global__ void copy_adj_tail_kernel(
    const int* __restrict__ adj, float* __restrict__ dst, int off, int n)
{
    int i = blockIdx.x * 256 + threadIdx.x;
    if (i < n) dst[off + i] = (float)adj[off + i];
}

extern "C" void kernel_launch(void* const* d_in, const int* in_sizes, int n_in,
                              void* d_out, int out_size)
{
    const float* x       = (const float*)d_in[0];
    const int*   adj     = (const int*)  d_in[1];
    const float* Wsrc    = (const float*)d_in[2];
    const float* Wtgt    = (const float*)d_in[3];
    const float* Wskip   = (const float*)d_in[4];
    const float* scoring = (const float*)d_in[5];
    const float* bias    = (const float*)d_in[6];
    float* out = (float*)d_out;

    gemm3_kernel<<<dim3(HD / 64, ROWS / 64, 3), 256>>>(x, Wsrc, Wtgt, Wskip, scoring);
    score_kernel<<<dim3(NN / 16, HEADS, BSZ), 512>>>(adj, scoring);
    agg_kernel<<<dim3(NN / 64, HEADS, BSZ), 256>>>(bias, out);

    const int main_elems = ROWS * HD;               // 524288
    if (out_size > main_elems) {
        int extra = out_size - main_elems;
        const int adj_elems = BSZ * NN * NN;        // 524288
        if (extra > adj_elems) extra = adj_elems;
        int n4 = extra >> 2;
        if (n4 > 0)
            copy_adj_vec_kernel<<<(n4 + 255) / 256, 256>>>(
                (const int4*)adj, (float4*)(out + main_elems), n4);
        int rem = extra - (n4 << 2);
        if (rem > 0)
            copy_adj_tail_kernel<<<1, 256>>>(adj, out + main_elems, n4 << 2, rem);
    }
}

// round 6
// speedup vs baseline: 1.5866x; 1.5866x over previous
#include <cuda_runtime.h>
#include <math.h>

#define BSZ   2
#define NN    512
#define DIN   256
#define HEADS 8
#define DOUT  64
#define HD    512
#define ROWS  1024
#define ALPHA 0.2f

// ---------------- packed fp32x2 helpers (Blackwell FADD2/FFMA2) ----------------
struct __align__(8) F2 { float x, y; };

__device__ __forceinline__ F2 f2add(F2 a, F2 b) {
    F2 r;
    asm("add.rn.f32x2 %0, %1, %2;"
        : "=l"(*reinterpret_cast<unsigned long long*>(&r))
        : "l"(*reinterpret_cast<unsigned long long*>(&a)),
          "l"(*reinterpret_cast<unsigned long long*>(&b)));
    return r;
}
__device__ __forceinline__ F2 f2fma(F2 a, F2 b, F2 c) {
    F2 r;
    asm("fma.rn.f32x2 %0, %1, %2, %3;"
        : "=l"(*reinterpret_cast<unsigned long long*>(&r))
        : "l"(*reinterpret_cast<unsigned long long*>(&a)),
          "l"(*reinterpret_cast<unsigned long long*>(&b)),
          "l"(*reinterpret_cast<unsigned long long*>(&c)));
    return r;
}

// ---------------- device scratch ----------------
__device__ float g_src [ROWS * HD];
__device__ float g_tgt [ROWS * HD];
__device__ float g_skip[ROWS * HD];
__device__ float g_asrc[BSZ * HEADS * NN];
__device__ float g_atgt[BSZ * HEADS * NN];

// ---------------------------------------------------------------------------
// K1: three projections (EXACT round-4 version, measured 24.9us)
// 64x64 tile, 128 threads, grid (8,16,3)=384 blocks.
// ---------------------------------------------------------------------------
#define APITCH 68
#define BPITCH 68

__global__ void __launch_bounds__(128) gemm3_kernel(
    const float* __restrict__ X,
    const float* __restrict__ Wsrc,
    const float* __restrict__ Wtgt,
    const float* __restrict__ Wskip,
    const float* __restrict__ scoring)
{
    __shared__ __align__(16) float As[32 * APITCH];  // [kk][n]
    __shared__ __align__(16) float Bs[32 * BPITCH];  // [kk][d]
    __shared__ float sh_sv[64];

    const int z = blockIdx.z;
    const float* W = (z == 0) ? Wsrc : (z == 1) ? Wtgt : Wskip;
    float* C = (z == 0) ? g_src : (z == 1) ? g_tgt : g_skip;

    const int rowBase = blockIdx.y * 64;
    const int colBase = blockIdx.x * 64;
    const int t  = threadIdx.x;

    const int nG = t >> 4;            // 0..7 -> 8 rows (4 n-pairs)
    const int dG = t & 15;            // 0..15 -> 4 cols
    const int r0 = nG * 8;
    const int d0 = dG * 4;

    const int ak = t & 31;
    const int an = t >> 5;
    const int bk = t >> 4;
    const int bd = (t & 15) * 4;

    if (t < 16)
        *(float4*)&sh_sv[t * 4] = *(const float4*)&scoring[colBase + t * 4];

    F2 acc[4][4];
#pragma unroll
    for (int p = 0; p < 4; p++)
#pragma unroll
        for (int j = 0; j < 4; j++) acc[p][j] = {0.f, 0.f};

    float  aR[16];
    float4 bR[4];

#pragma unroll
    for (int i = 0; i < 16; i++)
        aR[i] = X[(size_t)(rowBase + an + 4 * i) * DIN + ak];
#pragma unroll
    for (int i = 0; i < 4; i++)
        bR[i] = *(const float4*)&W[(size_t)(bk + 8 * i) * HD + colBase + bd];

    for (int s = 0; s < 8; s++) {
        __syncthreads();
#pragma unroll
        for (int i = 0; i < 16; i++)
            As[ak * APITCH + an + 4 * i] = aR[i];
#pragma unroll
        for (int i = 0; i < 4; i++)
            *(float4*)&Bs[(bk + 8 * i) * BPITCH + bd] = bR[i];
        __syncthreads();

        if (s < 7) {
            const int k0 = (s + 1) * 32;
#pragma unroll
            for (int i = 0; i < 16; i++)
                aR[i] = X[(size_t)(rowBase + an + 4 * i) * DIN + k0 + ak];
#pragma unroll
            for (int i = 0; i < 4; i++)
                bR[i] = *(const float4*)&W[(size_t)(k0 + bk + 8 * i) * HD + colBase + bd];
        }

#pragma unroll
        for (int k = 0; k < 32; k++) {
            float4 a01 = *(const float4*)&As[k * APITCH + r0];
            float4 a23 = *(const float4*)&As[k * APITCH + r0 + 4];
            float4 b   = *(const float4*)&Bs[k * BPITCH + d0];
            F2 ap[4] = {{a01.x, a01.y}, {a01.z, a01.w}, {a23.x, a23.y}, {a23.z, a23.w}};
            F2 bb[4] = {{b.x, b.x}, {b.y, b.y}, {b.z, b.z}, {b.w, b.w}};
#pragma unroll
            for (int p = 0; p < 4; p++)
#pragma unroll
                for (int j = 0; j < 4; j++)
                    acc[p][j] = f2fma(ap[p], bb[j], acc[p][j]);
        }
    }

#pragma unroll
    for (int p = 0; p < 4; p++) {
        float4 lo = make_float4(acc[p][0].x, acc[p][1].x, acc[p][2].x, acc[p][3].x);
        float4 hi = make_float4(acc[p][0].y, acc[p][1].y, acc[p][2].y, acc[p][3].y);
        *(float4*)&C[(size_t)(rowBase + r0 + 2 * p)     * HD + colBase + d0] = lo;
        *(float4*)&C[(size_t)(rowBase + r0 + 2 * p + 1) * HD + colBase + d0] = hi;
    }

    if (z < 2) {
        const float s0 = sh_sv[d0], s1 = sh_sv[d0 + 1],
                    s2 = sh_sv[d0 + 2], s3 = sh_sv[d0 + 3];
        float part[8];
#pragma unroll
        for (int p = 0; p < 4; p++) {
            part[2 * p]     = acc[p][0].x * s0 + acc[p][1].x * s1
                            + acc[p][2].x * s2 + acc[p][3].x * s3;
            part[2 * p + 1] = acc[p][0].y * s0 + acc[p][1].y * s1
                            + acc[p][2].y * s2 + acc[p][3].y * s3;
        }
#pragma unroll
        for (int o = 1; o <= 8; o <<= 1)
#pragma unroll
            for (int i = 0; i < 8; i++)
                part[i] += __shfl_xor_sync(0xffffffffu, part[i], o);
        if (dG == 0) {
            float* dst = (z == 0) ? g_asrc : g_atgt;
            const int hh = blockIdx.x;
#pragma unroll
            for (int i = 0; i < 8; i++) {
                int rG = rowBase + r0 + i;
                dst[((rG >> 9) * HEADS + hh) * NN + (rG & (NN - 1))] = part[i];
            }
        }
    }
}

// ---------------------------------------------------------------------------
// K2: fused scores + mask + softmax + aggregation + skip + bias + ELU
// Block = (16 query rows, head, batch); 512 threads. Grid (32, 8, 2).
// Phase 1: 2n x 8m per thread (acc = 32 regs). Phase 2: 16 m-groups x (4n x 8d).
// ---------------------------------------------------------------------------
#define PPITCH 517
#define TPITCH 10
#define VPITCH 68

__global__ void __launch_bounds__(512) attn_kernel(
    const int*   __restrict__ adj,
    const float* __restrict__ scoring,
    const float* __restrict__ bias,
    float*       __restrict__ out)
{
    __shared__ __align__(16) float BUF [16 * PPITCH];   // tgt stage -> probs -> overlay
    __shared__ __align__(16) float VBUF[64 * VPITCH];
    __shared__ __align__(16) float sh_src[16 * 64];
    __shared__ float sh_atgt[512];
    __shared__ __align__(16) float sh_s[64];
    __shared__ float sh_asrc[16];
    __shared__ float sh_inv[16];
    __shared__ float REDM[8][2][2];
    __shared__ float REDS[8][2][2];

    const int t  = threadIdx.x;
    const int bn = blockIdx.x * 16;
    const int h  = blockIdx.y;
    const int b  = blockIdx.z;
    const int bh = b * HEADS + h;

    const int nG = t >> 6;          // 0..7 (2 n each)
    const int mG = t & 63;          // m = mG + 64*mm
    const int wg = (t >> 5) & 1;    // warp within n-group

    // ---- prologue ----
    if (t < 16) {
        float4 v = *(const float4*)&scoring[h * 64 + t * 4];
        v.x *= (1.f - ALPHA); v.y *= (1.f - ALPHA);
        v.z *= (1.f - ALPHA); v.w *= (1.f - ALPHA);
        *(float4*)&sh_s[t * 4] = v;
        sh_asrc[t] = g_asrc[bh * NN + bn + t];
    }
    if (t < 256) {
        int r = t >> 4, c = t & 15;
        *(float4*)&sh_src[r * 64 + c * 4] =
            *(const float4*)&g_src[(size_t)(b * NN + bn + r) * HD + h * 64 + c * 4];
    }
    sh_atgt[t] = g_atgt[bh * NN + t];

    // ---- phase 1: scores (2n x 8m per thread, d chunks of 8, reg-prefetched) ----
    F2 acc[2][8];
#pragma unroll
    for (int i = 0; i < 2; i++)
#pragma unroll
        for (int mm = 0; mm < 8; mm++) acc[i][mm] = {0.f, 0.f};

    float4 pf[2];
#pragma unroll
    for (int q = 0; q < 2; q++) {
        int f4 = t + 512 * q;
        int row = f4 >> 1, half = f4 & 1;
        pf[q] = *(const float4*)&g_tgt[(size_t)(b * NN + row) * HD + h * 64 + half * 4];
    }

    for (int chunk = 0; chunk < 8; chunk++) {
        __syncthreads();
#pragma unroll
        for (int q = 0; q < 2; q++) {
            int f4 = t + 512 * q;
            int row = f4 >> 1, half = f4 & 1;
            int base = row * TPITCH + half * 4;
            *(F2*)&BUF[base]     = {pf[q].x, pf[q].y};
            *(F2*)&BUF[base + 2] = {pf[q].z, pf[q].w};
        }
        __syncthreads();

        if (chunk < 7) {
            const int c8 = (chunk + 1) * 8;
#pragma unroll
            for (int q = 0; q < 2; q++) {
                int f4 = t + 512 * q;
                int row = f4 >> 1, half = f4 & 1;
                pf[q] = *(const float4*)
                    &g_tgt[(size_t)(b * NN + row) * HD + h * 64 + c8 + half * 4];
            }
        }

#pragma unroll
        for (int j = 0; j < 4; j++) {
            F2 sj = *(const F2*)&sh_s[chunk * 8 + j * 2];
            F2 srcv[2];
#pragma unroll
            for (int i = 0; i < 2; i++)
                srcv[i] = *(const F2*)&sh_src[(nG * 2 + i) * 64 + chunk * 8 + j * 2];
#pragma unroll
            for (int mm = 0; mm < 8; mm++) {
                F2 tv = *(const F2*)&BUF[(mG + 64 * mm) * TPITCH + j * 2];
#pragma unroll
                for (int i = 0; i < 2; i++) {
                    F2 u = f2add(srcv[i], tv);
                    u.x = fmaxf(u.x, 0.f);
                    u.y = fmaxf(u.y, 0.f);
                    acc[i][mm] = f2fma(sj, u, acc[i][mm]);
                }
            }
        }
    }

    // ---- finalize scores (registers): alpha-term + mask; track max ----
    float a_n[2];
#pragma unroll
    for (int i = 0; i < 2; i++) a_n[i] = sh_asrc[nG * 2 + i];

    float rm[2] = {-3.4e38f, -3.4e38f};
#pragma unroll
    for (int mm = 0; mm < 8; mm++) {
        const int m = mG + 64 * mm;
        const float bm = sh_atgt[m];
#pragma unroll
        for (int i = 0; i < 2; i++) {
            float s = acc[i][mm].x + acc[i][mm].y;
            s = fmaf(ALPHA, a_n[i] + bm, s);
            int av = adj[(size_t)(b * NN + bn + nG * 2 + i) * NN + m];
            s = (av == 0) ? s - 1.0e9f : s;
            acc[i][mm].x = s;          // keep score in register
            rm[i] = fmaxf(rm[i], s);
        }
    }
#pragma unroll
    for (int i = 0; i < 2; i++)
#pragma unroll
        for (int o = 16; o; o >>= 1)
            rm[i] = fmaxf(rm[i], __shfl_xor_sync(0xffffffffu, rm[i], o));
    if ((t & 31) == 0) {
        REDM[nG][wg][0] = rm[0];
        REDM[nG][wg][1] = rm[1];
    }
    __syncthreads();   // also: BUF staging reads complete -> prob writes safe
#pragma unroll
    for (int i = 0; i < 2; i++) rm[i] = fmaxf(REDM[nG][0][i], REDM[nG][1][i]);

    // ---- exp (from registers) -> write probs to BUF; sum ----
    float ps[2] = {0.f, 0.f};
#pragma unroll
    for (int mm = 0; mm < 8; mm++) {
        const int m = mG + 64 * mm;
#pragma unroll
        for (int i = 0; i < 2; i++) {
            float e = __expf(acc[i][mm].x - rm[i]);
            BUF[(nG * 2 + i) * PPITCH + m] = e;
            ps[i] += e;
        }
    }
#pragma unroll
    for (int i = 0; i < 2; i++)
#pragma unroll
        for (int o = 16; o; o >>= 1)
            ps[i] += __shfl_xor_sync(0xffffffffu, ps[i], o);
    if ((t & 31) == 0) {
        REDS[nG][wg][0] = ps[0];
        REDS[nG][wg][1] = ps[1];
    }
    __syncthreads();
    if (t < 16)
        sh_inv[t] = 1.f / (REDS[t >> 1][0][t & 1] + REDS[t >> 1][1][t & 1]);

    // ---- phase 2: aggregation (16 m-groups, 4n x 8d per lane, 8 tiles of 64 m) ----
    const int g    = t >> 5;        // 0..15
    const int l    = t & 31;
    const int nSub = l >> 3;        // 0..3
    const int dSub = l & 7;         // 0..7

    F2 acc2[4][4];
#pragma unroll
    for (int i = 0; i < 4; i++)
#pragma unroll
        for (int j = 0; j < 4; j++) acc2[i][j] = {0.f, 0.f};

    float4 vf[2];
#pragma unroll
    for (int q = 0; q < 2; q++) {
        int f4 = t + 512 * q;
        int row = f4 >> 4, c = f4 & 15;
        vf[q] = *(const float4*)&g_src[(size_t)(b * NN + row) * HD + h * 64 + c * 4];
    }

    for (int tile = 0; tile < 8; tile++) {
        __syncthreads();
#pragma unroll
        for (int q = 0; q < 2; q++) {
            int f4 = t + 512 * q;
            int row = f4 >> 4, c = f4 & 15;
            *(float4*)&VBUF[row * VPITCH + c * 4] = vf[q];
        }
        __syncthreads();

        if (tile < 7) {
#pragma unroll
            for (int q = 0; q < 2; q++) {
                int f4 = t + 512 * q;
                int row = f4 >> 4, c = f4 & 15;
                vf[q] = *(const float4*)
                    &g_src[(size_t)(b * NN + (tile + 1) * 64 + row) * HD + h * 64 + c * 4];
            }
        }

#pragma unroll
        for (int mm = 0; mm < 4; mm++) {
            const int mloc = g * 4 + mm;
            const int m = tile * 64 + mloc;
            F2 vv[4];
#pragma unroll
            for (int j = 0; j < 4; j++)
                vv[j] = *(const F2*)&VBUF[mloc * VPITCH + dSub * 8 + 2 * j];
#pragma unroll
            for (int i = 0; i < 4; i++) {
                float p = BUF[(nSub * 4 + i) * PPITCH + m];
                F2 pp = {p, p};
#pragma unroll
                for (int j = 0; j < 4; j++)
                    acc2[i][j] = f2fma(pp, vv[j], acc2[i][j]);
            }
        }
    }

    // ---- two-stage reduction over 16 groups (probs in BUF now dead) ----
    __syncthreads();
    if (g >= 8) {
#pragma unroll
        for (int i = 0; i < 4; i++)
#pragma unroll
            for (int j = 0; j < 4; j++)
                *(F2*)&BUF[(g - 8) * 1024 + (nSub * 4 + i) * 64 + dSub * 8 + 2 * j]
                    = acc2[i][j];
    }
    __syncthreads();
    if (g < 8) {
#pragma unroll
        for (int i = 0; i < 4; i++)
#pragma unroll
            for (int j = 0; j < 4; j++) {
                F2 o = *(const F2*)&BUF[g * 1024 + (nSub * 4 + i) * 64 + dSub * 8 + 2 * j];
                acc2[i][j] = f2add(acc2[i][j], o);
                *(F2*)&BUF[g * 1024 + (nSub * 4 + i) * 64 + dSub * 8 + 2 * j] = acc2[i][j];
            }
    }
    __syncthreads();

    // ---- final reduce + epilogue (first 256 threads, 4 outputs each) ----
    if (t < 256) {
        const int oIdx = t * 4;
        const int n = oIdx >> 6, d = oIdx & 63;
        float4 s = make_float4(0.f, 0.f, 0.f, 0.f);
#pragma unroll
        for (int g2 = 0; g2 < 8; g2++) {
            float4 r = *(const float4*)&BUF[g2 * 1024 + oIdx];
            s.x += r.x; s.y += r.y; s.z += r.z; s.w += r.w;
        }
        const float inv = sh_inv[n];
        const size_t off = (size_t)(b * NN + bn + n) * HD + h * 64 + d;
        float4 sk = *(const float4*)&g_skip[off];
        float4 bi = *(const float4*)&bias[h * 64 + d];
        float4 o;
        o.x = fmaf(s.x, inv, sk.x + bi.x);
        o.y = fmaf(s.y, inv, sk.y + bi.y);
        o.z = fmaf(s.z, inv, sk.z + bi.z);
        o.w = fmaf(s.w, inv, sk.w + bi.w);
        o.x = (o.x > 0.f) ? o.x : expm1f(o.x);
        o.y = (o.y > 0.f) ? o.y : expm1f(o.y);
        o.z = (o.z > 0.f) ? o.z : expm1f(o.z);
        o.w = (o.w > 0.f) ? o.w : expm1f(o.w);
        *(float4*)&out[off] = o;
    }
}

// ---------------------------------------------------------------------------
// Optional second output: reference returns (out, adj)
// ---------------------------------------------------------------------------
__global__ void __launch_bounds__(256) copy_adj_vec_kernel(
    const int4* __restrict__ adj, float4* __restrict__ dst, int n4)
{
    int i = blockIdx.x * 256 + threadIdx.x;
    if (i < n4) {
        int4 v = adj[i];
        dst[i] = make_float4((float)v.x, (float)v.y, (float)v.z, (float)v.w);
    }
}
__global__ void copy_adj_tail_kernel(
    const int* __restrict__ adj, float* __restrict__ dst, int off, int n)
{
    int i = blockIdx.x * 256 + threadIdx.x;
    if (i < n) dst[off + i] = (float)adj[off + i];
}

extern "C" void kernel_launch(void* const* d_in, const int* in_sizes, int n_in,
                              void* d_out, int out_size)
{
    const float* x       = (const float*)d_in[0];
    const int*   adj     = (const int*)  d_in[1];
    const float* Wsrc    = (const float*)d_in[2];
    const float* Wtgt    = (const float*)d_in[3];
    const float* Wskip   = (const float*)d_in[4];
    const float* scoring = (const float*)d_in[5];
    const float* bias    = (const float*)d_in[6];
    float* out = (float*)d_out;

    gemm3_kernel<<<dim3(HD / 64, ROWS / 64, 3), 128>>>(x, Wsrc, Wtgt, Wskip, scoring);
    attn_kernel<<<dim3(NN / 16, HEADS, BSZ), 512>>>(adj, scoring, bias, out);

    const int main_elems = ROWS * HD;               // 524288
    if (out_size > main_elems) {
        int extra = out_size - main_elems;
        const int adj_elems = BSZ * NN * NN;        // 524288
        if (extra > adj_elems) extra = adj_elems;
        int n4 = extra >> 2;
        if (n4 > 0)
            copy_adj_vec_kernel<<<(n4 + 255) / 256, 256>>>(
                (const int4*)adj, (float4*)(out + main_elems), n4);
        int rem = extra - (n4 << 2);
        if (rem > 0)
            copy_adj_tail_kernel<<<1, 256>>>(adj, out + main_elems, n4 << 2, rem);
    }
}